// round 12
// baseline (speedup 1.0000x reference)
#include <cuda_runtime.h>
#include <math.h>
#include <stdint.h>

#define NNODES 8192
#define EEDGES 262144
#define INC    256
#define HH     8
#define CC     32
#define HCC    256
#define OUTC   32
#define FLAT   (NNODES * HCC)
#define NGEMVB 512
#define NEG    0.2f

// ---- scratch (device globals; zero-initialized at module load) ----
__device__ float g_xh[NNODES * HCC];
__device__ float g_asrc[NNODES * HH];
__device__ float g_adst[NNODES * HH];
__device__ int   g_deg[NNODES];          // zeroed by scan phase after use
__device__ int   g_cursor[NNODES];       // reset each replay before scatter
__device__ int   g_row[NNODES + 1];
__device__ int   g_elist[EEDGES];        // src ids, CSR by dst
__device__ float g_ypart[OUTC * NGEMVB]; // per-block partial dots
__device__ int   g_bar;                  // phase counter: 256 / 512 / 768->0

// -------------------------------------------------------------------------
// cp.async helpers
__device__ __forceinline__ void cpa16(void* smem, const void* gmem) {
    unsigned sa = (unsigned)__cvta_generic_to_shared(smem);
    asm volatile("cp.async.cg.shared.global [%0], [%1], 16;" :: "r"(sa), "l"(gmem));
}
__device__ __forceinline__ void cpa_commit() {
    asm volatile("cp.async.commit_group;");
}
template <int N> __device__ __forceinline__ void cpa_wait() {
    asm volatile("cp.async.wait_group %0;" :: "n"(N));
}

// -------------------------------------------------------------------------
// Fused CSR build: count -> (grid barrier) -> block-0 scan -> (grid barrier)
// -> scatter. 256 blocks x 256 threads, all co-resident.
__global__ __launch_bounds__(256) void k_csr(const int* __restrict__ ei) {
    __shared__ int wsum[8];
    int tid = threadIdx.x;
    int bid = blockIdx.x;
    int t = bid * 256 + tid;            // 0..65535, 4 edges each

    // cursor reset (first 8192 threads)
    if (t < NNODES) g_cursor[t] = 0;

    // ---- phase 1: count ----
    int4 s4 = ((const int4*)ei)[t];
    int4 d4 = ((const int4*)(ei + EEDGES))[t];
    atomicAdd(&g_deg[d4.x], 1);
    atomicAdd(&g_deg[d4.y], 1);
    atomicAdd(&g_deg[d4.z], 1);
    atomicAdd(&g_deg[d4.w], 1);

    __syncthreads();
    if (tid == 0) { __threadfence(); atomicAdd(&g_bar, 1); }

    if (bid == 0) {
        // wait for all counts
        if (tid == 0) { while (*(volatile int*)&g_bar < 256) __nanosleep(20); __threadfence(); }
        __syncthreads();
        // ---- phase 2: scan (256 threads x 32 nodes) ----
        int base = tid * 32;
        int vals[32];
        {
            const int4* dp = (const int4*)&g_deg[base];
#pragma unroll
            for (int i = 0; i < 8; i++) {
                int4 v = dp[i];
                vals[i * 4 + 0] = v.x; vals[i * 4 + 1] = v.y;
                vals[i * 4 + 2] = v.z; vals[i * 4 + 3] = v.w;
            }
        }
        int s = 0;
#pragma unroll
        for (int i = 0; i < 32; i++) { int tmp = vals[i]; vals[i] = s; s += tmp; }
        int lane = tid & 31, warp = tid >> 5;
        int sc = s;
#pragma unroll
        for (int o = 1; o < 32; o <<= 1) {
            int tt = __shfl_up_sync(0xffffffffu, sc, o);
            if (lane >= o) sc += tt;
        }
        if (lane == 31) wsum[warp] = sc;
        __syncthreads();
        if (warp == 0 && lane < 8) {
            int ws = wsum[lane];
#pragma unroll
            for (int o = 1; o < 8; o <<= 1) {
                int tt = __shfl_up_sync(0xffu, ws, o);
                if (lane >= o) ws += tt;
            }
            wsum[lane] = ws;
        }
        __syncthreads();
        int off = sc - s + (warp ? wsum[warp - 1] : 0);
        {
            int4* rp = (int4*)&g_row[base];
            int4* dp = (int4*)&g_deg[base];
            int4 z = make_int4(0, 0, 0, 0);
#pragma unroll
            for (int i = 0; i < 8; i++) {
                rp[i] = make_int4(off + vals[i * 4 + 0], off + vals[i * 4 + 1],
                                  off + vals[i * 4 + 2], off + vals[i * 4 + 3]);
                dp[i] = z;   // reset deg for next replay
            }
        }
        if (tid == 255) g_row[NNODES] = off + s;
        __threadfence();
        __syncthreads();
        if (tid == 0) atomicAdd(&g_bar, 256);   // release: scan done (-> 512)
    } else {
        if (tid == 0) { while (*(volatile int*)&g_bar < 512) __nanosleep(20); __threadfence(); }
        __syncthreads();
    }

    // ---- phase 3: scatter ----
    int p;
    p = atomicAdd(&g_cursor[d4.x], 1); g_elist[g_row[d4.x] + p] = s4.x;
    p = atomicAdd(&g_cursor[d4.y], 1); g_elist[g_row[d4.y] + p] = s4.y;
    p = atomicAdd(&g_cursor[d4.z], 1); g_elist[g_row[d4.z] + p] = s4.z;
    p = atomicAdd(&g_cursor[d4.w], 1); g_elist[g_row[d4.w] + p] = s4.w;

    __syncthreads();
    if (tid == 0) {
        __threadfence();
        int old = atomicAdd(&g_bar, 1);
        if (old == 767) atomicExch(&g_bar, 0);   // last block resets for replay
    }
}

// -------------------------------------------------------------------------
// tf32 tensor-core GEMM: xh = x @ lin_w^T
__device__ __forceinline__ uint32_t f2tf(float f) {
    uint32_t r;
    asm("cvt.rna.tf32.f32 %0, %1;" : "=r"(r) : "f"(f));
    return r;
}
__device__ __forceinline__ void mma_tf32(float& c0, float& c1, float& c2, float& c3,
                                         uint32_t a0, uint32_t a1, uint32_t a2, uint32_t a3,
                                         uint32_t b0, uint32_t b1) {
    asm volatile("mma.sync.aligned.m16n8k8.row.col.f32.tf32.tf32.f32 "
                 "{%0,%1,%2,%3},{%4,%5,%6,%7},{%8,%9},{%0,%1,%2,%3};"
                 : "+f"(c0), "+f"(c1), "+f"(c2), "+f"(c3)
                 : "r"(a0), "r"(a1), "r"(a2), "r"(a3), "r"(b0), "r"(b1));
}

#define GKP 36

__global__ __launch_bounds__(256) void k_gemm(const float* __restrict__ x,
                                              const float* __restrict__ w) {
    __shared__ uint32_t As[128][GKP];
    __shared__ uint32_t Bs[64][GKP];
    int tid = threadIdx.x;
    int warp = tid >> 5, lane = tid & 31;
    int g = lane >> 2, tg = lane & 3;
    int wm = warp >> 2;
    int wn = warp & 3;
    int m0 = blockIdx.x * 128;
    int n0 = blockIdx.y * 64;
    int arow = tid >> 3;
    int ac4  = tid & 7;

    float acc[4][2][4];
#pragma unroll
    for (int i = 0; i < 4; i++)
#pragma unroll
        for (int j = 0; j < 2; j++)
#pragma unroll
            for (int q = 0; q < 4; q++) acc[i][j][q] = 0.f;

    float4 pa[4], pb[2];
#pragma unroll
    for (int i = 0; i < 4; i++)
        pa[i] = *(const float4*)&x[(size_t)(m0 + arow + i * 32) * INC + ac4 * 4];
#pragma unroll
    for (int i = 0; i < 2; i++)
        pb[i] = *(const float4*)&w[(size_t)(n0 + arow + i * 32) * INC + ac4 * 4];

    for (int kt = 0; kt < 8; kt++) {
#pragma unroll
        for (int i = 0; i < 4; i++) {
            uint32_t* p = &As[arow + i * 32][ac4 * 4];
            p[0] = f2tf(pa[i].x); p[1] = f2tf(pa[i].y);
            p[2] = f2tf(pa[i].z); p[3] = f2tf(pa[i].w);
        }
#pragma unroll
        for (int i = 0; i < 2; i++) {
            uint32_t* p = &Bs[arow + i * 32][ac4 * 4];
            p[0] = f2tf(pb[i].x); p[1] = f2tf(pb[i].y);
            p[2] = f2tf(pb[i].z); p[3] = f2tf(pb[i].w);
        }
        __syncthreads();
        if (kt < 7) {
            int kb = (kt + 1) * 32;
#pragma unroll
            for (int i = 0; i < 4; i++)
                pa[i] = *(const float4*)&x[(size_t)(m0 + arow + i * 32) * INC + kb + ac4 * 4];
#pragma unroll
            for (int i = 0; i < 2; i++)
                pb[i] = *(const float4*)&w[(size_t)(n0 + arow + i * 32) * INC + kb + ac4 * 4];
        }
#pragma unroll
        for (int ks = 0; ks < 4; ks++) {
            int k0 = ks * 8;
            uint32_t af[4][4], bf[2][2];
#pragma unroll
            for (int mf = 0; mf < 4; mf++) {
                int r = wm * 64 + mf * 16 + g;
                af[mf][0] = As[r][k0 + tg];
                af[mf][1] = As[r + 8][k0 + tg];
                af[mf][2] = As[r][k0 + tg + 4];
                af[mf][3] = As[r + 8][k0 + tg + 4];
            }
#pragma unroll
            for (int nf = 0; nf < 2; nf++) {
                int cidx = wn * 16 + nf * 8 + g;
                bf[nf][0] = Bs[cidx][k0 + tg];
                bf[nf][1] = Bs[cidx][k0 + tg + 4];
            }
#pragma unroll
            for (int mf = 0; mf < 4; mf++)
#pragma unroll
                for (int nf = 0; nf < 2; nf++)
                    mma_tf32(acc[mf][nf][0], acc[mf][nf][1], acc[mf][nf][2], acc[mf][nf][3],
                             af[mf][0], af[mf][1], af[mf][2], af[mf][3],
                             bf[nf][0], bf[nf][1]);
        }
        __syncthreads();
    }
#pragma unroll
    for (int mf = 0; mf < 4; mf++) {
#pragma unroll
        for (int nf = 0; nf < 2; nf++) {
            int r = m0 + wm * 64 + mf * 16 + g;
            int c = n0 + wn * 16 + nf * 8 + tg * 2;
            *(float2*)&g_xh[(size_t)r * HCC + c] = make_float2(acc[mf][nf][0], acc[mf][nf][1]);
            *(float2*)&g_xh[(size_t)(r + 8) * HCC + c] = make_float2(acc[mf][nf][2], acc[mf][nf][3]);
        }
    }
}

// -------------------------------------------------------------------------
__global__ void k_attn(const float* __restrict__ att_src, const float* __restrict__ att_dst) {
    int n = blockIdx.x;
    int h = threadIdx.x >> 5;
    int c = threadIdx.x & 31;
    float v = g_xh[(size_t)n * HCC + h * CC + c];
    float s = v * att_src[h * CC + c];
    float d = v * att_dst[h * CC + c];
#pragma unroll
    for (int o = 16; o > 0; o >>= 1) {
        s += __shfl_xor_sync(0xffffffffu, s, o);
        d += __shfl_xor_sync(0xffffffffu, d, o);
    }
    if (c == 0) { g_asrc[n * HH + h] = s; g_adst[n * HH + h] = d; }
}

// -------------------------------------------------------------------------
// Fused node aggregation + output GEMV with cp.async prefetch of out_w.
// Dynamic smem: sbuf float4[1024] (16KB) + stag float4[4][256][4] (64KB).
__global__ __launch_bounds__(256) void k_nodegemv(const float* __restrict__ out_w,
                                                  const float* __restrict__ bias) {
    extern __shared__ float4 smem_dyn[];
    float4* sbuf = smem_dyn;            // 1024 float4
    float4* stag = smem_dyn + 1024;     // 4 stages x 256 thr x 4 float4
    int tid = threadIdx.x;
    int warp = tid >> 5, lane = tid & 31;
    int h = lane >> 2;
    int c4 = lane * 2;

    // gemv row pointers (addresses independent of phase A)
    int base = blockIdx.x * 4096;
    int c0 = warp * 4;
    const float4* w0 = (const float4*)(out_w + (size_t)(c0 + 0) * FLAT + base);
    const float4* w1 = (const float4*)(out_w + (size_t)(c0 + 1) * FLAT + base);
    const float4* w2 = (const float4*)(out_w + (size_t)(c0 + 2) * FLAT + base);
    const float4* w3 = (const float4*)(out_w + (size_t)(c0 + 3) * FLAT + base);

    // prologue: prefetch gemv stages 0..2 while aggregation runs
#pragma unroll
    for (int st = 0; st < 3; st++) {
        float4* dst = stag + ((size_t)st * 256 + tid) * 4;
        int idx = st * 32 + lane;
        cpa16(dst + 0, w0 + idx);
        cpa16(dst + 1, w1 + idx);
        cpa16(dst + 2, w2 + idx);
        cpa16(dst + 3, w3 + idx);
        cpa_commit();
    }

    // ---- phase A: aggregate 2 nodes per warp ----
    const float4* bias4 = (const float4*)bias;
    float4 b0 = bias4[c4], b1 = bias4[c4 + 1];
#pragma unroll
    for (int k = 0; k < 2; k++) {
        int n = blockIdx.x * 16 + warp * 2 + k;
        int row0 = g_row[n];
        int deg = g_row[n + 1] - row0;
        float adh = __ldg(&g_adst[n * HH + h]);

        float denom;
        float4 acc0, acc1;
        { // self loop first
            float v = g_asrc[n * HH + h] + adh;
            v = v > 0.f ? v : NEG * v;
            float ex = __expf(v);
            denom = ex;
            const float4* xs = (const float4*)&g_xh[(size_t)n * HCC];
            float4 v0 = xs[c4], v1 = xs[c4 + 1];
            acc0 = make_float4(ex * v0.x, ex * v0.y, ex * v0.z, ex * v0.w);
            acc1 = make_float4(ex * v1.x, ex * v1.y, ex * v1.z, ex * v1.w);
        }
#pragma unroll 8
        for (int i = 0; i < deg; i++) {
            int s = g_elist[row0 + i];
            float v = g_asrc[s * HH + h] + adh;
            v = v > 0.f ? v : NEG * v;
            float ex = __expf(v);
            denom += ex;
            const float4* xs = (const float4*)&g_xh[(size_t)s * HCC];
            float4 v0 = xs[c4], v1 = xs[c4 + 1];
            acc0.x += ex * v0.x; acc0.y += ex * v0.y; acc0.z += ex * v0.z; acc0.w += ex * v0.w;
            acc1.x += ex * v1.x; acc1.y += ex * v1.y; acc1.z += ex * v1.z; acc1.w += ex * v1.w;
        }
        float dinv = 1.f / denom;
        int ln = warp * 2 + k;
        sbuf[ln * 64 + c4]     = make_float4(acc0.x * dinv + b0.x, acc0.y * dinv + b0.y,
                                             acc0.z * dinv + b0.z, acc0.w * dinv + b0.w);
        sbuf[ln * 64 + c4 + 1] = make_float4(acc1.x * dinv + b1.x, acc1.y * dinv + b1.y,
                                             acc1.z * dinv + b1.z, acc1.w * dinv + b1.w);
    }
    __syncthreads();

    // ---- phase B: streaming gemv from staged smem ----
    float a0 = 0.f, a1 = 0.f, a2 = 0.f, a3 = 0.f;
#pragma unroll 1
    for (int it = 0; it < 29; it++) {
        { // issue stage it+3
            int st = it + 3;
            float4* dst = stag + ((size_t)(st & 3) * 256 + tid) * 4;
            int idx = st * 32 + lane;
            cpa16(dst + 0, w0 + idx);
            cpa16(dst + 1, w1 + idx);
            cpa16(dst + 2, w2 + idx);
            cpa16(dst + 3, w3 + idx);
            cpa_commit();
        }
        cpa_wait<3>();
        const float4* sp = stag + ((size_t)(it & 3) * 256 + tid) * 4;
        float4 f = sbuf[it * 32 + lane];
        float4 v0 = sp[0], v1 = sp[1], v2 = sp[2], v3 = sp[3];
        a0 += v0.x * f.x + v0.y * f.y + v0.z * f.z + v0.w * f.w;
        a1 += v1.x * f.x + v1.y * f.y + v1.z * f.z + v1.w * f.w;
        a2 += v2.x * f.x + v2.y * f.y + v2.z * f.z + v2.w * f.w;
        a3 += v3.x * f.x + v3.y * f.y + v3.z * f.z + v3.w * f.w;
    }
    // tail: it = 29, 30, 31
#pragma unroll
    for (int it = 29; it < 32; it++) {
        if (it == 29) cpa_wait<2>();
        else if (it == 30) cpa_wait<1>();
        else cpa_wait<0>();
        const float4* sp = stag + ((size_t)(it & 3) * 256 + tid) * 4;
        float4 f = sbuf[it * 32 + lane];
        float4 v0 = sp[0], v1 = sp[1], v2 = sp[2], v3 = sp[3];
        a0 += v0.x * f.x + v0.y * f.y + v0.z * f.z + v0.w * f.w;
        a1 += v1.x * f.x + v1.y * f.y + v1.z * f.z + v1.w * f.w;
        a2 += v2.x * f.x + v2.y * f.y + v2.z * f.z + v2.w * f.w;
        a3 += v3.x * f.x + v3.y * f.y + v3.z * f.z + v3.w * f.w;
    }
#pragma unroll
    for (int o = 16; o > 0; o >>= 1) {
        a0 += __shfl_xor_sync(0xffffffffu, a0, o);
        a1 += __shfl_xor_sync(0xffffffffu, a1, o);
        a2 += __shfl_xor_sync(0xffffffffu, a2, o);
        a3 += __shfl_xor_sync(0xffffffffu, a3, o);
    }
    if (lane == 0) {
        g_ypart[(size_t)(c0 + 0) * NGEMVB + blockIdx.x] = a0;
        g_ypart[(size_t)(c0 + 1) * NGEMVB + blockIdx.x] = a1;
        g_ypart[(size_t)(c0 + 2) * NGEMVB + blockIdx.x] = a2;
        g_ypart[(size_t)(c0 + 3) * NGEMVB + blockIdx.x] = a3;
    }
}

// -------------------------------------------------------------------------
__global__ __launch_bounds__(1024) void k_soft(const float* __restrict__ out_b,
                                               float* __restrict__ out) {
    __shared__ float sy[OUTC];
    int tid = threadIdx.x;
    int warp = tid >> 5, lane = tid & 31;
    float s = 0.f;
#pragma unroll
    for (int i = 0; i < NGEMVB / 32; i++)
        s += g_ypart[(size_t)warp * NGEMVB + i * 32 + lane];
#pragma unroll
    for (int o = 16; o > 0; o >>= 1) s += __shfl_xor_sync(0xffffffffu, s, o);
    if (lane == 0) sy[warp] = s + out_b[warp];
    __syncthreads();
    if (tid < 32) {
        float v = sy[tid];
        float m = v;
#pragma unroll
        for (int o = 16; o > 0; o >>= 1) m = fmaxf(m, __shfl_xor_sync(0xffffffffu, m, o));
        float ex = __expf(v - m);
        float sum = ex;
#pragma unroll
        for (int o = 16; o > 0; o >>= 1) sum += __shfl_xor_sync(0xffffffffu, sum, o);
        out[tid] = ex / sum;
    }
}

// -------------------------------------------------------------------------
#define NODEGEMV_SMEM (16384 + 65536)

extern "C" void kernel_launch(void* const* d_in, const int* in_sizes, int n_in,
                              void* d_out, int out_size) {
    const float* x       = (const float*)d_in[0];
    const int*   ei      = (const int*)d_in[1];
    const float* lin_w   = (const float*)d_in[2];
    const float* att_src = (const float*)d_in[3];
    const float* att_dst = (const float*)d_in[4];
    const float* bias    = (const float*)d_in[5];
    const float* out_w   = (const float*)d_in[6];
    const float* out_b   = (const float*)d_in[7];
    float* out = (float*)d_out;

    static cudaStream_t s2 = nullptr;
    static cudaEvent_t evFork = nullptr, evJoin = nullptr;
    if (s2 == nullptr) {
        cudaStreamCreateWithFlags(&s2, cudaStreamNonBlocking);
        cudaEventCreateWithFlags(&evFork, cudaEventDisableTiming);
        cudaEventCreateWithFlags(&evJoin, cudaEventDisableTiming);
        cudaFuncSetAttribute(k_nodegemv, cudaFuncAttributeMaxDynamicSharedMemorySize,
                             NODEGEMV_SMEM);
    }

    // fork: fused CSR build on s2 concurrently with gemm+attn
    cudaEventRecord(evFork, 0);
    cudaStreamWaitEvent(s2, evFork, 0);
    k_csr<<<256, 256, 0, s2>>>(ei);
    cudaEventRecord(evJoin, s2);

    k_gemm<<<dim3(NNODES / 128, HCC / 64), 256>>>(x, lin_w);
    k_attn<<<NNODES, 256>>>(att_src, att_dst);

    cudaStreamWaitEvent(0, evJoin, 0);
    k_nodegemv<<<NGEMVB, 256, NODEGEMV_SMEM>>>(out_w, bias);
    k_soft<<<1, 1024>>>(out_b, out);
}

// round 13
// speedup vs baseline: 1.2061x; 1.2061x over previous
#include <cuda_runtime.h>
#include <math.h>
#include <stdint.h>

#define NNODES 8192
#define EEDGES 262144
#define INC    256
#define HH     8
#define CC     32
#define HCC    256
#define OUTC   32
#define FLAT   (NNODES * HCC)
#define NCHUNK 512              // 512 chunks x 16 nodes
#define NPROD  128              // producer blocks
#define NEG    0.2f

// ---- scratch (device globals; zero-initialized at module load) ----
__device__ float g_xh[NNODES * HCC];
__device__ float g_asrc[NNODES * HH];
__device__ float g_adst[NNODES * HH];
__device__ int   g_deg[NNODES];
__device__ int   g_cursor[NNODES];
__device__ int   g_row[NNODES + 1];
__device__ int   g_elist[EEDGES];
__device__ float g_agg[NNODES * HCC];     // agg + bias, produced per chunk
__device__ int   g_flag[NCHUNK];          // chunk-ready flags (cleared in k_gemm)
__device__ float g_ypart[OUTC * NCHUNK];
__device__ int   g_bar;                   // csr phase counter

// -------------------------------------------------------------------------
// Fused CSR build: count -> (grid barrier) -> block-0 scan -> (grid barrier)
// -> scatter. 256 blocks x 256 threads, all co-resident.
__global__ __launch_bounds__(256) void k_csr(const int* __restrict__ ei) {
    __shared__ int wsum[8];
    int tid = threadIdx.x;
    int bid = blockIdx.x;
    int t = bid * 256 + tid;

    if (t < NNODES) g_cursor[t] = 0;

    int4 s4 = ((const int4*)ei)[t];
    int4 d4 = ((const int4*)(ei + EEDGES))[t];
    atomicAdd(&g_deg[d4.x], 1);
    atomicAdd(&g_deg[d4.y], 1);
    atomicAdd(&g_deg[d4.z], 1);
    atomicAdd(&g_deg[d4.w], 1);

    __syncthreads();
    if (tid == 0) { __threadfence(); atomicAdd(&g_bar, 1); }

    if (bid == 0) {
        if (tid == 0) { while (*(volatile int*)&g_bar < 256) __nanosleep(20); __threadfence(); }
        __syncthreads();
        int base = tid * 32;
        int vals[32];
        {
            const int4* dp = (const int4*)&g_deg[base];
#pragma unroll
            for (int i = 0; i < 8; i++) {
                int4 v = dp[i];
                vals[i * 4 + 0] = v.x; vals[i * 4 + 1] = v.y;
                vals[i * 4 + 2] = v.z; vals[i * 4 + 3] = v.w;
            }
        }
        int s = 0;
#pragma unroll
        for (int i = 0; i < 32; i++) { int tmp = vals[i]; vals[i] = s; s += tmp; }
        int lane = tid & 31, warp = tid >> 5;
        int sc = s;
#pragma unroll
        for (int o = 1; o < 32; o <<= 1) {
            int tt = __shfl_up_sync(0xffffffffu, sc, o);
            if (lane >= o) sc += tt;
        }
        if (lane == 31) wsum[warp] = sc;
        __syncthreads();
        if (warp == 0 && lane < 8) {
            int ws = wsum[lane];
#pragma unroll
            for (int o = 1; o < 8; o <<= 1) {
                int tt = __shfl_up_sync(0xffu, ws, o);
                if (lane >= o) ws += tt;
            }
            wsum[lane] = ws;
        }
        __syncthreads();
        int off = sc - s + (warp ? wsum[warp - 1] : 0);
        {
            int4* rp = (int4*)&g_row[base];
            int4* dp = (int4*)&g_deg[base];
            int4 z = make_int4(0, 0, 0, 0);
#pragma unroll
            for (int i = 0; i < 8; i++) {
                rp[i] = make_int4(off + vals[i * 4 + 0], off + vals[i * 4 + 1],
                                  off + vals[i * 4 + 2], off + vals[i * 4 + 3]);
                dp[i] = z;
            }
        }
        if (tid == 255) g_row[NNODES] = off + s;
        __threadfence();
        __syncthreads();
        if (tid == 0) atomicAdd(&g_bar, 256);
    } else {
        if (tid == 0) { while (*(volatile int*)&g_bar < 512) __nanosleep(20); __threadfence(); }
        __syncthreads();
    }

    int p;
    p = atomicAdd(&g_cursor[d4.x], 1); g_elist[g_row[d4.x] + p] = s4.x;
    p = atomicAdd(&g_cursor[d4.y], 1); g_elist[g_row[d4.y] + p] = s4.y;
    p = atomicAdd(&g_cursor[d4.z], 1); g_elist[g_row[d4.z] + p] = s4.z;
    p = atomicAdd(&g_cursor[d4.w], 1); g_elist[g_row[d4.w] + p] = s4.w;

    __syncthreads();
    if (tid == 0) {
        __threadfence();
        int old = atomicAdd(&g_bar, 1);
        if (old == 767) atomicExch(&g_bar, 0);
    }
}

// -------------------------------------------------------------------------
// tf32 tensor-core GEMM: xh = x @ lin_w^T. Block (0,0) also clears g_flag.
__device__ __forceinline__ uint32_t f2tf(float f) {
    uint32_t r;
    asm("cvt.rna.tf32.f32 %0, %1;" : "=r"(r) : "f"(f));
    return r;
}
__device__ __forceinline__ void mma_tf32(float& c0, float& c1, float& c2, float& c3,
                                         uint32_t a0, uint32_t a1, uint32_t a2, uint32_t a3,
                                         uint32_t b0, uint32_t b1) {
    asm volatile("mma.sync.aligned.m16n8k8.row.col.f32.tf32.tf32.f32 "
                 "{%0,%1,%2,%3},{%4,%5,%6,%7},{%8,%9},{%0,%1,%2,%3};"
                 : "+f"(c0), "+f"(c1), "+f"(c2), "+f"(c3)
                 : "r"(a0), "r"(a1), "r"(a2), "r"(a3), "r"(b0), "r"(b1));
}

#define GKP 36

__global__ __launch_bounds__(256) void k_gemm(const float* __restrict__ x,
                                              const float* __restrict__ w) {
    __shared__ uint32_t As[128][GKP];
    __shared__ uint32_t Bs[64][GKP];
    int tid = threadIdx.x;
    // clear producer/consumer flags for this replay (stream-ordered before k_pc)
    if (blockIdx.x == 0 && blockIdx.y == 0) {
        g_flag[tid] = 0;
        g_flag[tid + 256] = 0;
    }
    int warp = tid >> 5, lane = tid & 31;
    int g = lane >> 2, tg = lane & 3;
    int wm = warp >> 2;
    int wn = warp & 3;
    int m0 = blockIdx.x * 128;
    int n0 = blockIdx.y * 64;
    int arow = tid >> 3;
    int ac4  = tid & 7;

    float acc[4][2][4];
#pragma unroll
    for (int i = 0; i < 4; i++)
#pragma unroll
        for (int j = 0; j < 2; j++)
#pragma unroll
            for (int q = 0; q < 4; q++) acc[i][j][q] = 0.f;

    float4 pa[4], pb[2];
#pragma unroll
    for (int i = 0; i < 4; i++)
        pa[i] = *(const float4*)&x[(size_t)(m0 + arow + i * 32) * INC + ac4 * 4];
#pragma unroll
    for (int i = 0; i < 2; i++)
        pb[i] = *(const float4*)&w[(size_t)(n0 + arow + i * 32) * INC + ac4 * 4];

    for (int kt = 0; kt < 8; kt++) {
#pragma unroll
        for (int i = 0; i < 4; i++) {
            uint32_t* p = &As[arow + i * 32][ac4 * 4];
            p[0] = f2tf(pa[i].x); p[1] = f2tf(pa[i].y);
            p[2] = f2tf(pa[i].z); p[3] = f2tf(pa[i].w);
        }
#pragma unroll
        for (int i = 0; i < 2; i++) {
            uint32_t* p = &Bs[arow + i * 32][ac4 * 4];
            p[0] = f2tf(pb[i].x); p[1] = f2tf(pb[i].y);
            p[2] = f2tf(pb[i].z); p[3] = f2tf(pb[i].w);
        }
        __syncthreads();
        if (kt < 7) {
            int kb = (kt + 1) * 32;
#pragma unroll
            for (int i = 0; i < 4; i++)
                pa[i] = *(const float4*)&x[(size_t)(m0 + arow + i * 32) * INC + kb + ac4 * 4];
#pragma unroll
            for (int i = 0; i < 2; i++)
                pb[i] = *(const float4*)&w[(size_t)(n0 + arow + i * 32) * INC + kb + ac4 * 4];
        }
#pragma unroll
        for (int ks = 0; ks < 4; ks++) {
            int k0 = ks * 8;
            uint32_t af[4][4], bf[2][2];
#pragma unroll
            for (int mf = 0; mf < 4; mf++) {
                int r = wm * 64 + mf * 16 + g;
                af[mf][0] = As[r][k0 + tg];
                af[mf][1] = As[r + 8][k0 + tg];
                af[mf][2] = As[r][k0 + tg + 4];
                af[mf][3] = As[r + 8][k0 + tg + 4];
            }
#pragma unroll
            for (int nf = 0; nf < 2; nf++) {
                int cidx = wn * 16 + nf * 8 + g;
                bf[nf][0] = Bs[cidx][k0 + tg];
                bf[nf][1] = Bs[cidx][k0 + tg + 4];
            }
#pragma unroll
            for (int mf = 0; mf < 4; mf++)
#pragma unroll
                for (int nf = 0; nf < 2; nf++)
                    mma_tf32(acc[mf][nf][0], acc[mf][nf][1], acc[mf][nf][2], acc[mf][nf][3],
                             af[mf][0], af[mf][1], af[mf][2], af[mf][3],
                             bf[nf][0], bf[nf][1]);
        }
        __syncthreads();
    }
#pragma unroll
    for (int mf = 0; mf < 4; mf++) {
#pragma unroll
        for (int nf = 0; nf < 2; nf++) {
            int r = m0 + wm * 64 + mf * 16 + g;
            int c = n0 + wn * 16 + nf * 8 + tg * 2;
            *(float2*)&g_xh[(size_t)r * HCC + c] = make_float2(acc[mf][nf][0], acc[mf][nf][1]);
            *(float2*)&g_xh[(size_t)(r + 8) * HCC + c] = make_float2(acc[mf][nf][2], acc[mf][nf][3]);
        }
    }
}

// -------------------------------------------------------------------------
__global__ void k_attn(const float* __restrict__ att_src, const float* __restrict__ att_dst) {
    int n = blockIdx.x;
    int h = threadIdx.x >> 5;
    int c = threadIdx.x & 31;
    float v = g_xh[(size_t)n * HCC + h * CC + c];
    float s = v * att_src[h * CC + c];
    float d = v * att_dst[h * CC + c];
#pragma unroll
    for (int o = 16; o > 0; o >>= 1) {
        s += __shfl_xor_sync(0xffffffffu, s, o);
        d += __shfl_xor_sync(0xffffffffu, d, o);
    }
    if (c == 0) { g_asrc[n * HH + h] = s; g_adst[n * HH + h] = d; }
}

// -------------------------------------------------------------------------
// Producer/consumer kernel.
// Blocks 0..127: producers. Block b aggregates chunks {b, 128+b, 256+b, 384+b}
//   (16 nodes each, 2 nodes per warp), writes agg+bias to g_agg, sets flag.
// Blocks 128..511: consumers. Block 128+cb streams out_w for chunk cb
//   (and chunk cb+384 if cb<128), waiting on the flag.
__device__ __forceinline__ void consume_chunk(int chunk, int warp, int lane,
                                              const float* out_w) {
    if (threadIdx.x == 0) {
        while (((volatile int*)g_flag)[chunk] == 0) __nanosleep(128);
    }
    __syncthreads();
    __threadfence();   // acquire: order flag observation before agg reads
    int base = chunk * 4096;
    int c0 = warp * 4;
    const float4* f4 = (const float4*)&g_agg[base];
    const float4* w0 = (const float4*)(out_w + (size_t)(c0 + 0) * FLAT + base);
    const float4* w1 = (const float4*)(out_w + (size_t)(c0 + 1) * FLAT + base);
    const float4* w2 = (const float4*)(out_w + (size_t)(c0 + 2) * FLAT + base);
    const float4* w3 = (const float4*)(out_w + (size_t)(c0 + 3) * FLAT + base);
    float a0 = 0.f, a1 = 0.f, a2 = 0.f, a3 = 0.f;
#pragma unroll 8
    for (int it = 0; it < 32; it++) {
        int idx = it * 32 + lane;
        float4 f = __ldg(&f4[idx]);
        float4 v0 = __ldcs(&w0[idx]);
        float4 v1 = __ldcs(&w1[idx]);
        float4 v2 = __ldcs(&w2[idx]);
        float4 v3 = __ldcs(&w3[idx]);
        a0 += v0.x * f.x + v0.y * f.y + v0.z * f.z + v0.w * f.w;
        a1 += v1.x * f.x + v1.y * f.y + v1.z * f.z + v1.w * f.w;
        a2 += v2.x * f.x + v2.y * f.y + v2.z * f.z + v2.w * f.w;
        a3 += v3.x * f.x + v3.y * f.y + v3.z * f.z + v3.w * f.w;
    }
#pragma unroll
    for (int o = 16; o > 0; o >>= 1) {
        a0 += __shfl_xor_sync(0xffffffffu, a0, o);
        a1 += __shfl_xor_sync(0xffffffffu, a1, o);
        a2 += __shfl_xor_sync(0xffffffffu, a2, o);
        a3 += __shfl_xor_sync(0xffffffffu, a3, o);
    }
    if (lane == 0) {
        g_ypart[(size_t)(c0 + 0) * NCHUNK + chunk] = a0;
        g_ypart[(size_t)(c0 + 1) * NCHUNK + chunk] = a1;
        g_ypart[(size_t)(c0 + 2) * NCHUNK + chunk] = a2;
        g_ypart[(size_t)(c0 + 3) * NCHUNK + chunk] = a3;
    }
}

__global__ __launch_bounds__(256, 4) void k_pc(const float* __restrict__ out_w,
                                               const float* __restrict__ bias) {
    int tid = threadIdx.x;
    int warp = tid >> 5, lane = tid & 31;
    int bid = blockIdx.x;

    if (bid < NPROD) {
        // ---- producer ----
        int h = lane >> 2;
        int c4 = lane * 2;
        const float4* bias4 = (const float4*)bias;
        float4 b0 = bias4[c4], b1 = bias4[c4 + 1];
#pragma unroll 1
        for (int ck = 0; ck < 4; ck++) {
            int chunk = ck * NPROD + bid;
#pragma unroll
            for (int k = 0; k < 2; k++) {
                int n = chunk * 16 + warp * 2 + k;
                int row0 = g_row[n];
                int deg = g_row[n + 1] - row0;
                float adh = __ldg(&g_adst[n * HH + h]);

                float denom;
                float4 acc0, acc1;
                { // self loop
                    float v = g_asrc[n * HH + h] + adh;
                    v = v > 0.f ? v : NEG * v;
                    float ex = __expf(v);
                    denom = ex;
                    const float4* xs = (const float4*)&g_xh[(size_t)n * HCC];
                    float4 v0 = xs[c4], v1 = xs[c4 + 1];
                    acc0 = make_float4(ex * v0.x, ex * v0.y, ex * v0.z, ex * v0.w);
                    acc1 = make_float4(ex * v1.x, ex * v1.y, ex * v1.z, ex * v1.w);
                }
#pragma unroll 8
                for (int i = 0; i < deg; i++) {
                    int s = g_elist[row0 + i];
                    float v = g_asrc[s * HH + h] + adh;
                    v = v > 0.f ? v : NEG * v;
                    float ex = __expf(v);
                    denom += ex;
                    const float4* xs = (const float4*)&g_xh[(size_t)s * HCC];
                    float4 v0 = xs[c4], v1 = xs[c4 + 1];
                    acc0.x += ex * v0.x; acc0.y += ex * v0.y; acc0.z += ex * v0.z; acc0.w += ex * v0.w;
                    acc1.x += ex * v1.x; acc1.y += ex * v1.y; acc1.z += ex * v1.z; acc1.w += ex * v1.w;
                }
                float dinv = 1.f / denom;
                float4* op = (float4*)&g_agg[(size_t)n * HCC];
                op[c4]     = make_float4(acc0.x * dinv + b0.x, acc0.y * dinv + b0.y,
                                         acc0.z * dinv + b0.z, acc0.w * dinv + b0.w);
                op[c4 + 1] = make_float4(acc1.x * dinv + b1.x, acc1.y * dinv + b1.y,
                                         acc1.z * dinv + b1.z, acc1.w * dinv + b1.w);
            }
            __threadfence();
            __syncthreads();
            if (tid == 0) atomicExch(&g_flag[chunk], 1);
        }
    } else {
        // ---- consumer ----
        int cb = bid - NPROD;           // 0..383
        consume_chunk(cb, warp, lane, out_w);
        if (cb < NPROD) {
            __syncthreads();
            consume_chunk(cb + 384, warp, lane, out_w);
        }
    }
}

// -------------------------------------------------------------------------
__global__ __launch_bounds__(1024) void k_soft(const float* __restrict__ out_b,
                                               float* __restrict__ out) {
    __shared__ float sy[OUTC];
    int tid = threadIdx.x;
    int warp = tid >> 5, lane = tid & 31;
    float s = 0.f;
#pragma unroll
    for (int i = 0; i < NCHUNK / 32; i++)
        s += g_ypart[(size_t)warp * NCHUNK + i * 32 + lane];
#pragma unroll
    for (int o = 16; o > 0; o >>= 1) s += __shfl_xor_sync(0xffffffffu, s, o);
    if (lane == 0) sy[warp] = s + out_b[warp];
    __syncthreads();
    if (tid < 32) {
        float v = sy[tid];
        float m = v;
#pragma unroll
        for (int o = 16; o > 0; o >>= 1) m = fmaxf(m, __shfl_xor_sync(0xffffffffu, m, o));
        float ex = __expf(v - m);
        float sum = ex;
#pragma unroll
        for (int o = 16; o > 0; o >>= 1) sum += __shfl_xor_sync(0xffffffffu, sum, o);
        out[tid] = ex / sum;
    }
}

// -------------------------------------------------------------------------
extern "C" void kernel_launch(void* const* d_in, const int* in_sizes, int n_in,
                              void* d_out, int out_size) {
    const float* x       = (const float*)d_in[0];
    const int*   ei      = (const int*)d_in[1];
    const float* lin_w   = (const float*)d_in[2];
    const float* att_src = (const float*)d_in[3];
    const float* att_dst = (const float*)d_in[4];
    const float* bias    = (const float*)d_in[5];
    const float* out_w   = (const float*)d_in[6];
    const float* out_b   = (const float*)d_in[7];
    float* out = (float*)d_out;

    static cudaStream_t s2 = nullptr;
    static cudaEvent_t evFork = nullptr, evJoin = nullptr;
    if (s2 == nullptr) {
        cudaStreamCreateWithFlags(&s2, cudaStreamNonBlocking);
        cudaEventCreateWithFlags(&evFork, cudaEventDisableTiming);
        cudaEventCreateWithFlags(&evJoin, cudaEventDisableTiming);
    }

    // fork: fused CSR build on s2 concurrently with gemm+attn
    cudaEventRecord(evFork, 0);
    cudaStreamWaitEvent(s2, evFork, 0);
    k_csr<<<256, 256, 0, s2>>>(ei);
    cudaEventRecord(evJoin, s2);

    k_gemm<<<dim3(NNODES / 128, HCC / 64), 256>>>(x, lin_w);
    k_attn<<<NNODES, 256>>>(att_src, att_dst);

    cudaStreamWaitEvent(0, evJoin, 0);
    k_pc<<<NPROD + 384, 256>>>(out_w, bias);
    k_soft<<<1, 1024>>>(out_b, out);
}

// round 14
// speedup vs baseline: 1.4083x; 1.1676x over previous
#include <cuda_runtime.h>
#include <cuda_bf16.h>
#include <math.h>
#include <stdint.h>

#define NNODES 8192
#define EEDGES 262144
#define INC    256
#define HH     8
#define CC     32
#define HCC    256
#define OUTC   32
#define FLAT   (NNODES * HCC)
#define NGEMVB 512
#define NEG    0.2f
#define PFLINES 48   // 48 x 128B lines = 1536 floats = 37.5% of each 4096-chunk-row

// ---- scratch (device globals; zero-initialized at module load) ----
__device__ float g_xh[NNODES * HCC];          // fp32 projected features (attn)
__device__ unsigned g_xhb[NNODES * (HCC/2)];  // bf16x2 packed copy (aggregation)
__device__ float g_asrc[NNODES * HH];
__device__ float g_adst[NNODES * HH];
__device__ int   g_deg[NNODES];
__device__ int   g_cursor[NNODES];
__device__ int   g_row[NNODES + 1];
__device__ int   g_elist[EEDGES];
__device__ float g_ypart[OUTC * NGEMVB];
__device__ int   g_bar;

// -------------------------------------------------------------------------
// L2 prefetch of out_w's first PFLINES lines per (row, chunk) slice.
__global__ __launch_bounds__(256) void k_pref(const float* __restrict__ out_w) {
    int chunk = blockIdx.x;
    int tid = threadIdx.x;
    const char* base = (const char*)(out_w + (size_t)chunk * 4096);
    for (int i = tid; i < 32 * PFLINES; i += 256) {
        int row = i / PFLINES;
        int line = i - row * PFLINES;
        const char* p = base + (size_t)row * (FLAT * 4) + line * 128;
        asm volatile("prefetch.global.L2 [%0];" :: "l"(p));
    }
}

// -------------------------------------------------------------------------
// Fused CSR build: count -> barrier -> block-0 scan -> barrier -> scatter.
__global__ __launch_bounds__(256) void k_csr(const int* __restrict__ ei) {
    __shared__ int wsum[8];
    int tid = threadIdx.x;
    int bid = blockIdx.x;
    int t = bid * 256 + tid;

    if (t < NNODES) g_cursor[t] = 0;

    int4 s4 = ((const int4*)ei)[t];
    int4 d4 = ((const int4*)(ei + EEDGES))[t];
    atomicAdd(&g_deg[d4.x], 1);
    atomicAdd(&g_deg[d4.y], 1);
    atomicAdd(&g_deg[d4.z], 1);
    atomicAdd(&g_deg[d4.w], 1);

    __syncthreads();
    if (tid == 0) { __threadfence(); atomicAdd(&g_bar, 1); }

    if (bid == 0) {
        if (tid == 0) { while (*(volatile int*)&g_bar < 256) __nanosleep(20); __threadfence(); }
        __syncthreads();
        int base = tid * 32;
        int vals[32];
        {
            const int4* dp = (const int4*)&g_deg[base];
#pragma unroll
            for (int i = 0; i < 8; i++) {
                int4 v = dp[i];
                vals[i * 4 + 0] = v.x; vals[i * 4 + 1] = v.y;
                vals[i * 4 + 2] = v.z; vals[i * 4 + 3] = v.w;
            }
        }
        int s = 0;
#pragma unroll
        for (int i = 0; i < 32; i++) { int tmp = vals[i]; vals[i] = s; s += tmp; }
        int lane = tid & 31, warp = tid >> 5;
        int sc = s;
#pragma unroll
        for (int o = 1; o < 32; o <<= 1) {
            int tt = __shfl_up_sync(0xffffffffu, sc, o);
            if (lane >= o) sc += tt;
        }
        if (lane == 31) wsum[warp] = sc;
        __syncthreads();
        if (warp == 0 && lane < 8) {
            int ws = wsum[lane];
#pragma unroll
            for (int o = 1; o < 8; o <<= 1) {
                int tt = __shfl_up_sync(0xffu, ws, o);
                if (lane >= o) ws += tt;
            }
            wsum[lane] = ws;
        }
        __syncthreads();
        int off = sc - s + (warp ? wsum[warp - 1] : 0);
        {
            int4* rp = (int4*)&g_row[base];
            int4* dp = (int4*)&g_deg[base];
            int4 z = make_int4(0, 0, 0, 0);
#pragma unroll
            for (int i = 0; i < 8; i++) {
                rp[i] = make_int4(off + vals[i * 4 + 0], off + vals[i * 4 + 1],
                                  off + vals[i * 4 + 2], off + vals[i * 4 + 3]);
                dp[i] = z;
            }
        }
        if (tid == 255) g_row[NNODES] = off + s;
        __threadfence();
        __syncthreads();
        if (tid == 0) atomicAdd(&g_bar, 256);
    } else {
        if (tid == 0) { while (*(volatile int*)&g_bar < 512) __nanosleep(20); __threadfence(); }
        __syncthreads();
    }

    int p;
    p = atomicAdd(&g_cursor[d4.x], 1); g_elist[g_row[d4.x] + p] = s4.x;
    p = atomicAdd(&g_cursor[d4.y], 1); g_elist[g_row[d4.y] + p] = s4.y;
    p = atomicAdd(&g_cursor[d4.z], 1); g_elist[g_row[d4.z] + p] = s4.z;
    p = atomicAdd(&g_cursor[d4.w], 1); g_elist[g_row[d4.w] + p] = s4.w;

    __syncthreads();
    if (tid == 0) {
        __threadfence();
        int old = atomicAdd(&g_bar, 1);
        if (old == 767) atomicExch(&g_bar, 0);
    }
}

// -------------------------------------------------------------------------
// tf32 tensor-core GEMM: xh = x @ lin_w^T; epilogue writes fp32 + bf16 copies.
__device__ __forceinline__ uint32_t f2tf(float f) {
    uint32_t r;
    asm("cvt.rna.tf32.f32 %0, %1;" : "=r"(r) : "f"(f));
    return r;
}
__device__ __forceinline__ void mma_tf32(float& c0, float& c1, float& c2, float& c3,
                                         uint32_t a0, uint32_t a1, uint32_t a2, uint32_t a3,
                                         uint32_t b0, uint32_t b1) {
    asm volatile("mma.sync.aligned.m16n8k8.row.col.f32.tf32.tf32.f32 "
                 "{%0,%1,%2,%3},{%4,%5,%6,%7},{%8,%9},{%0,%1,%2,%3};"
                 : "+f"(c0), "+f"(c1), "+f"(c2), "+f"(c3)
                 : "r"(a0), "r"(a1), "r"(a2), "r"(a3), "r"(b0), "r"(b1));
}

#define GKP 36

__global__ __launch_bounds__(256) void k_gemm(const float* __restrict__ x,
                                              const float* __restrict__ w) {
    __shared__ uint32_t As[128][GKP];
    __shared__ uint32_t Bs[64][GKP];
    int tid = threadIdx.x;
    int warp = tid >> 5, lane = tid & 31;
    int g = lane >> 2, tg = lane & 3;
    int wm = warp >> 2;
    int wn = warp & 3;
    int m0 = blockIdx.x * 128;
    int n0 = blockIdx.y * 64;
    int arow = tid >> 3;
    int ac4  = tid & 7;

    float acc[4][2][4];
#pragma unroll
    for (int i = 0; i < 4; i++)
#pragma unroll
        for (int j = 0; j < 2; j++)
#pragma unroll
            for (int q = 0; q < 4; q++) acc[i][j][q] = 0.f;

    float4 pa[4], pb[2];
#pragma unroll
    for (int i = 0; i < 4; i++)
        pa[i] = *(const float4*)&x[(size_t)(m0 + arow + i * 32) * INC + ac4 * 4];
#pragma unroll
    for (int i = 0; i < 2; i++)
        pb[i] = *(const float4*)&w[(size_t)(n0 + arow + i * 32) * INC + ac4 * 4];

    for (int kt = 0; kt < 8; kt++) {
#pragma unroll
        for (int i = 0; i < 4; i++) {
            uint32_t* p = &As[arow + i * 32][ac4 * 4];
            p[0] = f2tf(pa[i].x); p[1] = f2tf(pa[i].y);
            p[2] = f2tf(pa[i].z); p[3] = f2tf(pa[i].w);
        }
#pragma unroll
        for (int i = 0; i < 2; i++) {
            uint32_t* p = &Bs[arow + i * 32][ac4 * 4];
            p[0] = f2tf(pb[i].x); p[1] = f2tf(pb[i].y);
            p[2] = f2tf(pb[i].z); p[3] = f2tf(pb[i].w);
        }
        __syncthreads();
        if (kt < 7) {
            int kb = (kt + 1) * 32;
#pragma unroll
            for (int i = 0; i < 4; i++)
                pa[i] = *(const float4*)&x[(size_t)(m0 + arow + i * 32) * INC + kb + ac4 * 4];
#pragma unroll
            for (int i = 0; i < 2; i++)
                pb[i] = *(const float4*)&w[(size_t)(n0 + arow + i * 32) * INC + kb + ac4 * 4];
        }
#pragma unroll
        for (int ks = 0; ks < 4; ks++) {
            int k0 = ks * 8;
            uint32_t af[4][4], bf[2][2];
#pragma unroll
            for (int mf = 0; mf < 4; mf++) {
                int r = wm * 64 + mf * 16 + g;
                af[mf][0] = As[r][k0 + tg];
                af[mf][1] = As[r + 8][k0 + tg];
                af[mf][2] = As[r][k0 + tg + 4];
                af[mf][3] = As[r + 8][k0 + tg + 4];
            }
#pragma unroll
            for (int nf = 0; nf < 2; nf++) {
                int cidx = wn * 16 + nf * 8 + g;
                bf[nf][0] = Bs[cidx][k0 + tg];
                bf[nf][1] = Bs[cidx][k0 + tg + 4];
            }
#pragma unroll
            for (int mf = 0; mf < 4; mf++)
#pragma unroll
                for (int nf = 0; nf < 2; nf++)
                    mma_tf32(acc[mf][nf][0], acc[mf][nf][1], acc[mf][nf][2], acc[mf][nf][3],
                             af[mf][0], af[mf][1], af[mf][2], af[mf][3],
                             bf[nf][0], bf[nf][1]);
        }
        __syncthreads();
    }
#pragma unroll
    for (int mf = 0; mf < 4; mf++) {
#pragma unroll
        for (int nf = 0; nf < 2; nf++) {
            int r = m0 + wm * 64 + mf * 16 + g;
            int c = n0 + wn * 16 + nf * 8 + tg * 2;
            *(float2*)&g_xh[(size_t)r * HCC + c] = make_float2(acc[mf][nf][0], acc[mf][nf][1]);
            *(float2*)&g_xh[(size_t)(r + 8) * HCC + c] = make_float2(acc[mf][nf][2], acc[mf][nf][3]);
            __nv_bfloat162 h0 = __float22bfloat162_rn(make_float2(acc[mf][nf][0], acc[mf][nf][1]));
            __nv_bfloat162 h1 = __float22bfloat162_rn(make_float2(acc[mf][nf][2], acc[mf][nf][3]));
            ((__nv_bfloat162*)g_xhb)[(size_t)r * (HCC/2) + c / 2] = h0;
            ((__nv_bfloat162*)g_xhb)[(size_t)(r + 8) * (HCC/2) + c / 2] = h1;
        }
    }
}

// -------------------------------------------------------------------------
__global__ void k_attn(const float* __restrict__ att_src, const float* __restrict__ att_dst) {
    int n = blockIdx.x;
    int h = threadIdx.x >> 5;
    int c = threadIdx.x & 31;
    float v = g_xh[(size_t)n * HCC + h * CC + c];
    float s = v * att_src[h * CC + c];
    float d = v * att_dst[h * CC + c];
#pragma unroll
    for (int o = 16; o > 0; o >>= 1) {
        s += __shfl_xor_sync(0xffffffffu, s, o);
        d += __shfl_xor_sync(0xffffffffu, d, o);
    }
    if (c == 0) { g_asrc[n * HH + h] = s; g_adst[n * HH + h] = d; }
}

// -------------------------------------------------------------------------
// Fused node aggregation (bf16 gathers) + output GEMV (fp32 streaming).
__global__ __launch_bounds__(256) void k_nodegemv(const float* __restrict__ out_w,
                                                  const float* __restrict__ bias) {
    __shared__ float4 sbuf[1024];   // 16 nodes x 256 channels (agg + bias)
    int tid = threadIdx.x;
    int warp = tid >> 5, lane = tid & 31;
    int h = lane >> 2;
    int c4 = lane * 2;
    const float4* bias4 = (const float4*)bias;
    float4 b0 = bias4[c4], b1 = bias4[c4 + 1];
    const uint4* xb = (const uint4*)g_xhb;   // 32 uint4 per node; lane -> idx lane

#pragma unroll
    for (int k = 0; k < 2; k++) {
        int n = blockIdx.x * 16 + warp * 2 + k;
        int row0 = g_row[n];
        int deg = g_row[n + 1] - row0;
        float adh = __ldg(&g_adst[n * HH + h]);

        float denom;
        float4 acc0, acc1;
        { // self loop
            float v = g_asrc[n * HH + h] + adh;
            v = v > 0.f ? v : NEG * v;
            float ex = __expf(v);
            denom = ex;
            uint4 q = xb[(size_t)n * 32 + lane];
            float2 f0 = __bfloat1622float2(*(__nv_bfloat162*)&q.x);
            float2 f1 = __bfloat1622float2(*(__nv_bfloat162*)&q.y);
            float2 f2 = __bfloat1622float2(*(__nv_bfloat162*)&q.z);
            float2 f3 = __bfloat1622float2(*(__nv_bfloat162*)&q.w);
            acc0 = make_float4(ex * f0.x, ex * f0.y, ex * f1.x, ex * f1.y);
            acc1 = make_float4(ex * f2.x, ex * f2.y, ex * f3.x, ex * f3.y);
        }
#pragma unroll 8
        for (int i = 0; i < deg; i++) {
            int s = g_elist[row0 + i];
            float v = g_asrc[s * HH + h] + adh;
            v = v > 0.f ? v : NEG * v;
            float ex = __expf(v);
            denom += ex;
            uint4 q = xb[(size_t)s * 32 + lane];
            float2 f0 = __bfloat1622float2(*(__nv_bfloat162*)&q.x);
            float2 f1 = __bfloat1622float2(*(__nv_bfloat162*)&q.y);
            float2 f2 = __bfloat1622float2(*(__nv_bfloat162*)&q.z);
            float2 f3 = __bfloat1622float2(*(__nv_bfloat162*)&q.w);
            acc0.x += ex * f0.x; acc0.y += ex * f0.y; acc0.z += ex * f1.x; acc0.w += ex * f1.y;
            acc1.x += ex * f2.x; acc1.y += ex * f2.y; acc1.z += ex * f3.x; acc1.w += ex * f3.y;
        }
        float dinv = 1.f / denom;
        int ln = warp * 2 + k;
        sbuf[ln * 64 + c4]     = make_float4(acc0.x * dinv + b0.x, acc0.y * dinv + b0.y,
                                             acc0.z * dinv + b0.z, acc0.w * dinv + b0.w);
        sbuf[ln * 64 + c4 + 1] = make_float4(acc1.x * dinv + b1.x, acc1.y * dinv + b1.y,
                                             acc1.z * dinv + b1.z, acc1.w * dinv + b1.w);
    }
    __syncthreads();

    // streaming gemv: warp w -> output rows [4w, 4w+4)
    int base = blockIdx.x * 4096;
    int c0 = warp * 4;
    const float4* w0 = (const float4*)(out_w + (size_t)(c0 + 0) * FLAT + base);
    const float4* w1 = (const float4*)(out_w + (size_t)(c0 + 1) * FLAT + base);
    const float4* w2 = (const float4*)(out_w + (size_t)(c0 + 2) * FLAT + base);
    const float4* w3 = (const float4*)(out_w + (size_t)(c0 + 3) * FLAT + base);
    float a0 = 0.f, a1 = 0.f, a2 = 0.f, a3 = 0.f;
#pragma unroll 8
    for (int it = 0; it < 32; it++) {
        int idx = it * 32 + lane;
        float4 f = sbuf[idx];
        float4 v0 = __ldcs(&w0[idx]);
        float4 v1 = __ldcs(&w1[idx]);
        float4 v2 = __ldcs(&w2[idx]);
        float4 v3 = __ldcs(&w3[idx]);
        a0 += v0.x * f.x + v0.y * f.y + v0.z * f.z + v0.w * f.w;
        a1 += v1.x * f.x + v1.y * f.y + v1.z * f.z + v1.w * f.w;
        a2 += v2.x * f.x + v2.y * f.y + v2.z * f.z + v2.w * f.w;
        a3 += v3.x * f.x + v3.y * f.y + v3.z * f.z + v3.w * f.w;
    }
#pragma unroll
    for (int o = 16; o > 0; o >>= 1) {
        a0 += __shfl_xor_sync(0xffffffffu, a0, o);
        a1 += __shfl_xor_sync(0xffffffffu, a1, o);
        a2 += __shfl_xor_sync(0xffffffffu, a2, o);
        a3 += __shfl_xor_sync(0xffffffffu, a3, o);
    }
    if (lane == 0) {
        g_ypart[(size_t)(c0 + 0) * NGEMVB + blockIdx.x] = a0;
        g_ypart[(size_t)(c0 + 1) * NGEMVB + blockIdx.x] = a1;
        g_ypart[(size_t)(c0 + 2) * NGEMVB + blockIdx.x] = a2;
        g_ypart[(size_t)(c0 + 3) * NGEMVB + blockIdx.x] = a3;
    }
}

// -------------------------------------------------------------------------
__global__ __launch_bounds__(1024) void k_soft(const float* __restrict__ out_b,
                                               float* __restrict__ out) {
    __shared__ float sy[OUTC];
    int tid = threadIdx.x;
    int warp = tid >> 5, lane = tid & 31;
    float s = 0.f;
#pragma unroll
    for (int i = 0; i < NGEMVB / 32; i++)
        s += g_ypart[(size_t)warp * NGEMVB + i * 32 + lane];
#pragma unroll
    for (int o = 16; o > 0; o >>= 1) s += __shfl_xor_sync(0xffffffffu, s, o);
    if (lane == 0) sy[warp] = s + out_b[warp];
    __syncthreads();
    if (tid < 32) {
        float v = sy[tid];
        float m = v;
#pragma unroll
        for (int o = 16; o > 0; o >>= 1) m = fmaxf(m, __shfl_xor_sync(0xffffffffu, m, o));
        float ex = __expf(v - m);
        float sum = ex;
#pragma unroll
        for (int o = 16; o > 0; o >>= 1) sum += __shfl_xor_sync(0xffffffffu, sum, o);
        out[tid] = ex / sum;
    }
}

// -------------------------------------------------------------------------
extern "C" void kernel_launch(void* const* d_in, const int* in_sizes, int n_in,
                              void* d_out, int out_size) {
    const float* x       = (const float*)d_in[0];
    const int*   ei      = (const int*)d_in[1];
    const float* lin_w   = (const float*)d_in[2];
    const float* att_src = (const float*)d_in[3];
    const float* att_dst = (const float*)d_in[4];
    const float* bias    = (const float*)d_in[5];
    const float* out_w   = (const float*)d_in[6];
    const float* out_b   = (const float*)d_in[7];
    float* out = (float*)d_out;

    static cudaStream_t s2 = nullptr, s3 = nullptr;
    static cudaEvent_t evFork = nullptr, evJoin = nullptr, evJoin3 = nullptr;
    if (s2 == nullptr) {
        cudaStreamCreateWithFlags(&s2, cudaStreamNonBlocking);
        cudaStreamCreateWithFlags(&s3, cudaStreamNonBlocking);
        cudaEventCreateWithFlags(&evFork, cudaEventDisableTiming);
        cudaEventCreateWithFlags(&evJoin, cudaEventDisableTiming);
        cudaEventCreateWithFlags(&evJoin3, cudaEventDisableTiming);
    }

    cudaEventRecord(evFork, 0);
    // s2: fused CSR build
    cudaStreamWaitEvent(s2, evFork, 0);
    k_csr<<<256, 256, 0, s2>>>(ei);
    cudaEventRecord(evJoin, s2);
    // s3: out_w L2 prefetch (hint only)
    cudaStreamWaitEvent(s3, evFork, 0);
    k_pref<<<NGEMVB, 256, 0, s3>>>(out_w);
    cudaEventRecord(evJoin3, s3);

    // main: projection + attention dots
    k_gemm<<<dim3(NNODES / 128, HCC / 64), 256>>>(x, lin_w);
    k_attn<<<NNODES, 256>>>(att_src, att_dst);

    cudaStreamWaitEvent(0, evJoin, 0);
    cudaStreamWaitEvent(0, evJoin3, 0);
    k_nodegemv<<<NGEMVB, 256>>>(out_w, bias);
    k_soft<<<1, 1024>>>(out_b, out);
}